// round 14
// baseline (speedup 1.0000x reference)
#include <cuda_runtime.h>
#include <cuda_bf16.h>
#include <cuda_pipeline.h>
#include <mma.h>
#include <math.h>

using namespace nvcuda;

#define B_   8
#define C_   256
#define P_   4096
#define CP_  1048576
#define KC_  4608
#define STAGE_E 12288   /* bf16 elements per stage (24KB) */
#define NSTG 4

/* ---------------- scratch (static device globals; no allocs) ------------- */
__device__ float          g_qf [B_*CP_];
__device__ __nv_bfloat16  g_qh [B_*CP_];
__device__ __nv_bfloat16  g_ql [B_*CP_];
__device__ __nv_bfloat16  g_kvh[B_*CP_];
__device__ __nv_bfloat16  g_kvl[B_*CP_];
__device__ float          g_t1 [B_*CP_];
__device__ float          g_off[B_*2*P_];
__device__ __nv_bfloat16  g_sph[B_*CP_];
__device__ __nv_bfloat16  g_spl[B_*CP_];
__device__ float          g_x1 [B_*CP_];
__device__ __nv_bfloat16  g_hnh[B_*CP_];
__device__ __nv_bfloat16  g_hnl[B_*CP_];
__device__ __nv_bfloat16  g_h1h[B_*P_*1024];
__device__ __nv_bfloat16  g_h1l[B_*P_*1024];
__device__ __nv_bfloat16  g_wrh[C_*KC_];
__device__ __nv_bfloat16  g_wrl[C_*KC_];
__device__ __nv_bfloat16  g_f1h[1024*C_];
__device__ __nv_bfloat16  g_f1l[1024*C_];
__device__ __nv_bfloat16  g_f2h[C_*1024];
__device__ __nv_bfloat16  g_f2l[C_*1024];
__device__ __nv_bfloat16  g_wch[C_*C_];
__device__ __nv_bfloat16  g_wcl[C_*C_];
__device__ float          g_bc [C_];
__device__ double         g_ps [24][64];
__device__ double         g_pq [24][64];
__device__ float          g_mean[24];
__device__ float          g_rstd[24];
/* tap -> (dy+1)*16 + (dx+1); decode with shifts */
__device__ const int g_tap[9] = {0, 1, 2, 16, 17, 18, 32, 33, 34};

__device__ __forceinline__ void split2(float a, __nv_bfloat16* h, __nv_bfloat16* l) {
    __nv_bfloat16 hh = __float2bfloat16(a);
    *h = hh;
    *l = __float2bfloat16(a - __bfloat162float(hh));
}

/* ------------------------------- GN stats -------------------------------- */
__global__ void gn_reduce2(const float* xa, const float* xb, int so, int use_x1) {
    int b = blockIdx.y, z = blockIdx.z;
    const float* src = (use_x1 != 0) ? (const float*)g_x1 : (z == 0 ? xa : xb);
    const float* xp = src + (size_t)b * CP_;
    double s = 0.0, s2 = 0.0;
    for (int i = blockIdx.x * blockDim.x + threadIdx.x; i < CP_;
         i += gridDim.x * blockDim.x) {
        float v = xp[i];
        s += (double)v; s2 += (double)v * (double)v;
    }
    __shared__ double sh[256];
    __shared__ double sh2[256];
    int t = threadIdx.x;
    sh[t] = s; sh2[t] = s2;
    __syncthreads();
    for (int o = 128; o > 0; o >>= 1) {
        if (t < o) { sh[t] += sh[t + o]; sh2[t] += sh2[t + o]; }
        __syncthreads();
    }
    if (t == 0) {
        int slot = so + z * 8 + b;
        g_ps[slot][blockIdx.x] = sh[0];
        g_pq[slot][blockIdx.x] = sh2[0];
    }
}

__global__ void finalize_stats(int s0) {
    int slot = s0 + blockIdx.x;
    int t = threadIdx.x;   /* 64 threads */
    __shared__ double sh[64];
    __shared__ double sh2[64];
    sh[t] = g_ps[slot][t];
    sh2[t] = g_pq[slot][t];
    __syncthreads();
    for (int o = 32; o > 0; o >>= 1) {
        if (t < o) { sh[t] += sh[t + o]; sh2[t] += sh2[t + o]; }
        __syncthreads();
    }
    if (t == 0) {
        double mu  = sh[0] / (double)CP_;
        double var = sh2[0] / (double)CP_ - mu * mu;
        g_mean[slot] = (float)mu;
        g_rstd[slot] = rsqrtf((float)var + 1e-5f);
    }
}

/* -- GN apply + NCHW->NHWC transpose + split, BOTH tensors in one launch -- */
__global__ void gn_apply_fused(const float* xq, const float* xkv,
                               const float* w, const float* bb) {
    __shared__ float t[32][33];
    int z = blockIdx.z;
    int b = z & 7, which = z >> 3;
    const float* x = which ? xkv : xq;
    float m = g_mean[which * 8 + b], rs = g_rstd[which * 8 + b];
    int p0 = blockIdx.x * 32, c0 = blockIdx.y * 32;
    int tx = threadIdx.x, ty = threadIdx.y;
    const float* xb = x + (size_t)b * CP_;
    for (int i = ty; i < 32; i += 8) {
        int c = c0 + i;
        t[i][tx] = (xb[(size_t)c * P_ + p0 + tx] - m) * rs * w[c] + bb[c];
    }
    __syncthreads();
    size_t ob = (size_t)b * CP_;
    for (int i = ty; i < 32; i += 8) {
        float v = t[tx][i];
        size_t o = ob + (size_t)(p0 + i) * C_ + c0 + tx;
        if (which == 0) {
            g_qf[o] = v;
            split2(v, &g_qh[o], &g_ql[o]);
        } else {
            split2(v, &g_kvh[o], &g_kvl[o]);
        }
    }
}

__global__ void gn2_apply(int so, const float* w, const float* bb) {
    int b = blockIdx.y;
    float m = g_mean[so + b], rs = g_rstd[so + b];
    const float* xb = g_x1 + (size_t)b * CP_;
    size_t ob = (size_t)b * CP_;
    for (int i = blockIdx.x * blockDim.x + threadIdx.x; i < CP_;
         i += gridDim.x * blockDim.x) {
        int c = i & 255;
        float v = (xb[i] - m) * rs * w[c] + bb[c];
        split2(v, &g_hnh[ob + i], &g_hnl[ob + i]);
    }
}

/* --------------------------- weight preparation -------------------------- */
__global__ void prep_split(const float* src, int n, int wsel) {
    int i = blockIdx.x * blockDim.x + threadIdx.x;
    if (i < n) {
        if (wsel == 1) split2(src[i], &g_f1h[i], &g_f1l[i]);
        else           split2(src[i], &g_f2h[i], &g_f2l[i]);
    }
}

__global__ void prep_conv_w(const float* src) {
    int i = blockIdx.x * blockDim.x + threadIdx.x;
    if (i < C_ * KC_) {
        int o = i / KC_, k = i - o * KC_;
        int tap = k >> 9, cc = k & 511;
        float v = src[(size_t)o * KC_ + (size_t)cc * 9 + tap];
        split2(v, &g_wrh[i], &g_wrl[i]);
    }
}

__global__ void combine_w(const float* pw, const float* pb,
                          const float* kw, const float* kb) {
    int idx = blockIdx.x * blockDim.x + threadIdx.x;
    if (idx < 65536) {
        int o = idx >> 8, c = idx & 255;
        float s = 0.f;
        for (int j = 0; j < 256; j++)
            s += pw[o * 256 + j] * kw[(256 + j) * 256 + c];
        split2(s, &g_wch[idx], &g_wcl[idx]);
    } else if (idx < 65536 + 256) {
        int o = idx - 65536;
        float s = pb[o];
        for (int j = 0; j < 256; j++)
            s += pw[o * 256 + j] * kb[256 + j];
        g_bc[o] = s;
    }
}

/* ==== split-bf16 wmma GEMM, CTA 128x128, BK=16, 4-stage cp.async ========= */
__global__ __launch_bounds__(256, 2)
void gemm_wmma(int cfg, const float* bias_ext, const float* res_ext, float* out_ext) {
    extern __shared__ __align__(32) char smd[];
    __nv_bfloat16* base = (__nv_bfloat16*)smd;
    float* stP = (float*)smd;

    int K = (cfg == 3) ? 1024 : 256;
    int N = (cfg == 2) ? 1024 : 256;
    const __nv_bfloat16* Ah;
    const __nv_bfloat16* Al;
    const __nv_bfloat16* Bh;
    const __nv_bfloat16* Bl;
    const float* bias;
    if (cfg == 1)      { Ah = g_sph; Al = g_spl; Bh = g_wch; Bl = g_wcl; bias = g_bc; }
    else if (cfg == 2) { Ah = g_hnh; Al = g_hnl; Bh = g_f1h; Bl = g_f1l; bias = bias_ext; }
    else               { Ah = g_h1h; Al = g_h1l; Bh = g_f2h; Bl = g_f2l; bias = bias_ext; }

    int tid = threadIdx.x, lane = tid & 31, wrp = tid >> 5;
    int wm = (wrp >> 2) * 64, wn = (wrp & 3) * 32;
    int b  = blockIdx.z;
    int m0 = blockIdx.x * 128, n0 = blockIdx.y * 128;
    size_t asb = (size_t)P_ * K;
    const __nv_bfloat16* Ahb = Ah + (size_t)b * asb;
    const __nv_bfloat16* Alb = Al + (size_t)b * asb;

    wmma::fragment<wmma::accumulator, 16, 16, 16, float> acc[4][2];
    for (int i = 0; i < 4; i++)
        for (int j = 0; j < 2; j++)
            wmma::fill_fragment(acc[i][j], 0.0f);

    int row = tid >> 1, c8 = (tid & 1) * 8;
    size_t aoff = (size_t)(m0 + row) * K + c8;
    size_t boff = (size_t)(n0 + row) * K + c8;
    int nk = K >> 4;
    int sidx = row * 24 + c8;

    /* prologue: slabs 0..2 into stages 0..2 */
    for (int p = 0; p < 3 && p < nk; p++) {
        __nv_bfloat16* sg = base + p * STAGE_E;
        int ko = p << 4;
        __pipeline_memcpy_async(sg + sidx,        Ahb + aoff + ko, 16);
        __pipeline_memcpy_async(sg + 3072 + sidx, Alb + aoff + ko, 16);
        __pipeline_memcpy_async(sg + 6144 + sidx, Bh + boff + ko, 16);
        __pipeline_memcpy_async(sg + 9216 + sidx, Bl + boff + ko, 16);
        __pipeline_commit();
    }

    for (int ks = 0;; ks++) {
        __pipeline_wait_prior(2);
        __syncthreads();
        __nv_bfloat16* sg = base + (ks & 3) * STAGE_E;
        wmma::fragment<wmma::matrix_b, 16, 16, 16, __nv_bfloat16, wmma::col_major> fbh0, fbh1, fbl0, fbl1;
        wmma::load_matrix_sync(fbh0, sg + 6144 + wn * 24, 24);
        wmma::load_matrix_sync(fbh1, sg + 6144 + (wn + 16) * 24, 24);
        wmma::load_matrix_sync(fbl0, sg + 9216 + wn * 24, 24);
        wmma::load_matrix_sync(fbl1, sg + 9216 + (wn + 16) * 24, 24);
        for (int i = 0; i < 4; i++) {
            wmma::fragment<wmma::matrix_a, 16, 16, 16, __nv_bfloat16, wmma::row_major> fah, fal;
            wmma::load_matrix_sync(fah, sg + (wm + i * 16) * 24, 24);
            wmma::load_matrix_sync(fal, sg + 3072 + (wm + i * 16) * 24, 24);
            wmma::mma_sync(acc[i][0], fah, fbh0, acc[i][0]);
            wmma::mma_sync(acc[i][0], fah, fbl0, acc[i][0]);
            wmma::mma_sync(acc[i][0], fal, fbh0, acc[i][0]);
            wmma::mma_sync(acc[i][1], fah, fbh1, acc[i][1]);
            wmma::mma_sync(acc[i][1], fah, fbl1, acc[i][1]);
            wmma::mma_sync(acc[i][1], fal, fbh1, acc[i][1]);
        }
        if (ks + 1 >= nk) break;
        if (ks + 3 < nk) {
            __nv_bfloat16* sn = base + ((ks + 3) & 3) * STAGE_E;
            int ko = (ks + 3) << 4;
            __pipeline_memcpy_async(sn + sidx,        Ahb + aoff + ko, 16);
            __pipeline_memcpy_async(sn + 3072 + sidx, Alb + aoff + ko, 16);
            __pipeline_memcpy_async(sn + 6144 + sidx, Bh + boff + ko, 16);
            __pipeline_memcpy_async(sn + 9216 + sidx, Bl + boff + ko, 16);
        }
        __pipeline_commit();
    }

    __pipeline_wait_prior(0);
    __syncthreads();   /* stage memory dead; alias as epilogue staging */

    int r2 = lane >> 1, cB = (lane & 1) * 8;
    float* stw = stP + wrp * 320;
    for (int i = 0; i < 4; i++) {
        for (int j = 0; j < 2; j++) {
            wmma::store_matrix_sync(stw, acc[i][j], 20, wmma::mem_row_major);
            __syncwarp();
            int m = m0 + wm + i * 16 + r2;
            int n = n0 + wn + j * 16 + cB;
            for (int c = 0; c < 8; c++) {
                float v = stw[r2 * 20 + cB + c] + bias[n + c];
                if (cfg == 1) {
                    v += res_ext[(size_t)b * CP_ + (size_t)(n + c) * P_ + m];
                    g_x1[(size_t)b * CP_ + (size_t)m * C_ + n + c] = v;
                } else if (cfg == 2) {
                    v = 0.5f * v * (1.0f + erff(v * 0.70710678118654752f));
                    size_t o = (size_t)b * (size_t)P_ * N + (size_t)m * N + n + c;
                    split2(v, &g_h1h[o], &g_h1l[o]);
                } else {
                    v += g_x1[(size_t)b * CP_ + (size_t)m * C_ + n + c];
                    out_ext[(size_t)b * CP_ + (size_t)(n + c) * P_ + m] = v;
                }
            }
            __syncwarp();
        }
    }
}

/* ---- conv3x3 implicit GEMM (wmma), K tap-major, 4-stage cp.async -------- */
__device__ __forceinline__ void conv_issue_slab(
    int kn, __nv_bfloat16* sg, int sidx, int ph, int pw, int c8,
    size_t bbase, size_t boff) {
    int tap = kn >> 9, cc = (kn & 511) + c8;
    int e = g_tap[tap];
    int hh = ph + (e >> 4) - 1, ww = pw + (e & 15) - 1;
    if (hh >= 0 && hh < 64 && ww >= 0 && ww < 64) {
        size_t base = bbase + (size_t)((hh << 6) + ww) * C_;
        if (cc < 256) {
            __pipeline_memcpy_async(sg + sidx,        g_kvh + base + cc, 16);
            __pipeline_memcpy_async(sg + 3072 + sidx, g_kvl + base + cc, 16);
        } else {
            __pipeline_memcpy_async(sg + sidx,        g_qh + base + cc - 256, 16);
            __pipeline_memcpy_async(sg + 3072 + sidx, g_ql + base + cc - 256, 16);
        }
    } else {
        __pipeline_memcpy_async(sg + sidx,        g_kvh, 16, 16);
        __pipeline_memcpy_async(sg + 3072 + sidx, g_kvl, 16, 16);
    }
    __pipeline_memcpy_async(sg + 6144 + sidx, g_wrh + boff + kn, 16);
    __pipeline_memcpy_async(sg + 9216 + sidx, g_wrl + boff + kn, 16);
}

__global__ __launch_bounds__(256, 2)
void conv_wmma(const float* bias) {
    extern __shared__ __align__(32) char smd[];
    __nv_bfloat16* base = (__nv_bfloat16*)smd;
    float* stP = (float*)smd;

    int tid = threadIdx.x, lane = tid & 31, wrp = tid >> 5;
    int wm = (wrp >> 2) * 64, wn = (wrp & 3) * 32;
    int b  = blockIdx.z;
    int m0 = blockIdx.x * 128, n0 = blockIdx.y * 128;

    wmma::fragment<wmma::accumulator, 16, 16, 16, float> acc[4][2];
    for (int i = 0; i < 4; i++)
        for (int j = 0; j < 2; j++)
            wmma::fill_fragment(acc[i][j], 0.0f);

    int row = tid >> 1, c8 = (tid & 1) * 8;
    int pix = m0 + row, ph = pix >> 6, pw = pix & 63;
    size_t bbase = (size_t)b * CP_;
    size_t boff = (size_t)(n0 + row) * KC_ + c8;
    const int nk = KC_ >> 4;
    int sidx = row * 24 + c8;

    for (int p = 0; p < 3; p++) {
        conv_issue_slab(p << 4, base + p * STAGE_E, sidx, ph, pw, c8, bbase, boff);
        __pipeline_commit();
    }

    for (int ks = 0;; ks++) {
        __pipeline_wait_prior(2);
        __syncthreads();
        __nv_bfloat16* sg = base + (ks & 3) * STAGE_E;
        wmma::fragment<wmma::matrix_b, 16, 16, 16, __nv_bfloat16, wmma::col_major> fbh0, fbh1, fbl0, fbl1;
        wmma::load_matrix_sync(fbh0, sg + 6144 + wn * 24, 24);
        wmma::load_matrix_sync(fbh1, sg + 6144 + (wn + 16) * 24, 24);
        wmma::load_matrix_sync(fbl0, sg + 9216 + wn * 24, 24);
        wmma::load_matrix_sync(fbl1, sg + 9216 + (wn + 16) * 24, 24);
        for (int i = 0; i < 4; i++) {
            wmma::fragment<wmma::matrix_a, 16, 16, 16, __nv_bfloat16, wmma::row_major> fah, fal;
            wmma::load_matrix_sync(fah, sg + (wm + i * 16) * 24, 24);
            wmma::load_matrix_sync(fal, sg + 3072 + (wm + i * 16) * 24, 24);
            wmma::mma_sync(acc[i][0], fah, fbh0, acc[i][0]);
            wmma::mma_sync(acc[i][0], fah, fbl0, acc[i][0]);
            wmma::mma_sync(acc[i][0], fal, fbh0, acc[i][0]);
            wmma::mma_sync(acc[i][1], fah, fbh1, acc[i][1]);
            wmma::mma_sync(acc[i][1], fah, fbl1, acc[i][1]);
            wmma::mma_sync(acc[i][1], fal, fbh1, acc[i][1]);
        }
        if (ks + 1 >= nk) break;
        if (ks + 3 < nk)
            conv_issue_slab((ks + 3) << 4, base + ((ks + 3) & 3) * STAGE_E,
                            sidx, ph, pw, c8, bbase, boff);
        __pipeline_commit();
    }

    __pipeline_wait_prior(0);
    __syncthreads();

    int r2 = lane >> 1, cB = (lane & 1) * 8;
    float* stw = stP + wrp * 320;
    for (int i = 0; i < 4; i++) {
        for (int j = 0; j < 2; j++) {
            wmma::store_matrix_sync(stw, acc[i][j], 20, wmma::mem_row_major);
            __syncwarp();
            int m = m0 + wm + i * 16 + r2;
            int n = n0 + wn + j * 16 + cB;
            for (int c = 0; c < 8; c++) {
                float v = stw[r2 * 20 + cB + c] + bias[n + c];
                g_t1[bbase + (size_t)m * C_ + n + c] = fmaxf(v, 0.f);
            }
            __syncwarp();
        }
    }
}

/* --------------------- offset head: 256 -> 2 (NHWC) ---------------------- */
__global__ void off_kernel(const float* w2, const float* b2) {
    int gid = blockIdx.x * blockDim.x + threadIdx.x;
    int pix = gid >> 5, lane = gid & 31;
    int b = pix >> 12, p = pix & 4095;
    const float* t = g_t1 + (size_t)b * CP_ + (size_t)p * C_;
    float s0 = 0.f, s1 = 0.f;
    for (int c0 = 0; c0 < 256; c0 += 32) {
        float v = t[c0 + lane];
        s0 += w2[c0 + lane] * v;
        s1 += w2[256 + c0 + lane] * v;
    }
    for (int o = 16; o > 0; o >>= 1) {
        s0 += __shfl_xor_sync(0xffffffffu, s0, o);
        s1 += __shfl_xor_sync(0xffffffffu, s1, o);
    }
    if (lane == 0) {
        g_off[b * 2 * P_ + p]      = s0 + b2[0];
        g_off[b * 2 * P_ + P_ + p] = s1 + b2[1];
    }
}

/* ----------------- bilinear grid-sample (zeros pad), NHWC ---------------- */
__global__ void sample_kernel() {
    int gid = blockIdx.x * blockDim.x + threadIdx.x;
    int pix = gid >> 5, lane = gid & 31;
    int b = pix >> 12, p = pix & 4095;
    float ox = g_off[b * 2 * P_ + p];
    float oy = g_off[b * 2 * P_ + P_ + p];
    float gx = ox / 63.0f * 2.0f - 1.0f;
    float gy = oy / 63.0f * 2.0f - 1.0f;
    float ix = (gx + 1.0f) * 0.5f * 63.0f;
    float iy = (gy + 1.0f) * 0.5f * 63.0f;
    float x0f = floorf(ix), y0f = floorf(iy);
    float wx1 = ix - x0f, wx0 = 1.0f - wx1;
    float wy1 = iy - y0f, wy0 = 1.0f - wy1;
    int x0 = (int)x0f,          y0 = (int)y0f;
    int x1 = (int)(x0f + 1.0f), y1 = (int)(y0f + 1.0f);
    bool vx0 = (x0 >= 0 && x0 < 64), vx1 = (x1 >= 0 && x1 < 64);
    bool vy0 = (y0 >= 0 && y0 < 64), vy1 = (y1 >= 0 && y1 < 64);
    float e00 = (vy0 && vx0) ? wy0 * wx0 : 0.f;
    float e01 = (vy0 && vx1) ? wy0 * wx1 : 0.f;
    float e10 = (vy1 && vx0) ? wy1 * wx0 : 0.f;
    float e11 = (vy1 && vx1) ? wy1 * wx1 : 0.f;
    int xc0 = min(max(x0, 0), 63), xc1 = min(max(x1, 0), 63);
    int yc0 = min(max(y0, 0), 63), yc1 = min(max(y1, 0), 63);
    const float* base = g_qf + (size_t)b * CP_;
    const float* p00 = base + (size_t)((yc0 << 6) + xc0) * C_;
    const float* p01 = base + (size_t)((yc0 << 6) + xc1) * C_;
    const float* p10 = base + (size_t)((yc1 << 6) + xc0) * C_;
    const float* p11 = base + (size_t)((yc1 << 6) + xc1) * C_;
    size_t o = (size_t)b * CP_ + (size_t)p * C_;
    for (int c = lane; c < C_; c += 32) {
        float v = e00 * p00[c] + e01 * p01[c] + e10 * p10[c] + e11 * p11[c];
        split2(v, &g_sph[o + c], &g_spl[o + c]);
    }
}

/* ------------------------------ launch ----------------------------------- */
extern "C" void kernel_launch(void* const* d_in, const int* in_sizes, int n_in,
                              void* d_out, int out_size) {
    const float* x_q    = (const float*)d_in[0];
    const float* x_kv   = (const float*)d_in[1];
    const float* n1_w   = (const float*)d_in[2];
    const float* n1_b   = (const float*)d_in[3];
    const float* kv_w   = (const float*)d_in[6];
    const float* kv_b   = (const float*)d_in[7];
    const float* off1_w = (const float*)d_in[8];
    const float* off1_b = (const float*)d_in[9];
    const float* off2_w = (const float*)d_in[10];
    const float* off2_b = (const float*)d_in[11];
    const float* proj_w = (const float*)d_in[12];
    const float* proj_b = (const float*)d_in[13];
    const float* n2_w   = (const float*)d_in[14];
    const float* n2_b   = (const float*)d_in[15];
    const float* fc1_w  = (const float*)d_in[16];
    const float* fc1_b  = (const float*)d_in[17];
    const float* fc2_w  = (const float*)d_in[18];
    const float* fc2_b  = (const float*)d_in[19];

    const int SMEM4 = NSTG * 24576;   /* 96KB dynamic */
    static int attr_done = 0;
    if (!attr_done) {
        cudaFuncSetAttribute(gemm_wmma, cudaFuncAttributeMaxDynamicSharedMemorySize, SMEM4);
        cudaFuncSetAttribute(conv_wmma, cudaFuncAttributeMaxDynamicSharedMemorySize, SMEM4);
        attr_done = 1;
    }

    /* fork side stream for independent weight-prep work */
    cudaStream_t s0 = 0;
    static cudaStream_t s1 = 0;
    if (!s1) cudaStreamCreateWithFlags(&s1, cudaStreamNonBlocking);
    static cudaEvent_t evFork = 0, evPrep = 0;
    if (!evFork) {
        cudaEventCreateWithFlags(&evFork, cudaEventDisableTiming);
        cudaEventCreateWithFlags(&evPrep, cudaEventDisableTiming);
    }

    cudaEventRecord(evFork, s0);
    cudaStreamWaitEvent(s1, evFork, 0);
    /* side stream: all weight prep (independent of activations) */
    prep_conv_w<<<(C_ * KC_ + 255) / 256, 256, 0, s1>>>(off1_w);
    prep_split<<<(1024 * C_ + 255) / 256, 256, 0, s1>>>(fc1_w, 1024 * C_, 1);
    prep_split<<<(C_ * 1024 + 255) / 256, 256, 0, s1>>>(fc2_w, C_ * 1024, 2);
    combine_w<<<(65536 + 256 + 255) / 256, 256, 0, s1>>>(proj_w, proj_b, kv_w, kv_b);
    cudaEventRecord(evPrep, s1);

    /* main stream: activation path */
    gn_reduce2<<<dim3(64, 8, 2), 256, 0, s0>>>(x_q, x_kv, 0, 0);
    finalize_stats<<<16, 64, 0, s0>>>(0);
    gn_apply_fused<<<dim3(128, 8, 16), dim3(32, 8), 0, s0>>>(x_q, x_kv, n1_w, n1_b);
    cudaStreamWaitEvent(s0, evPrep, 0);    /* conv needs g_wr*; v-GEMM needs g_wc* */
    conv_wmma<<<dim3(32, 2, 8), 256, SMEM4, s0>>>(off1_b);
    off_kernel<<<(B_ * P_ * 32) / 256, 256, 0, s0>>>(off2_w, off2_b);
    sample_kernel<<<(B_ * P_ * 32) / 256, 256, 0, s0>>>();
    gemm_wmma<<<dim3(32, 2, 8), 256, SMEM4, s0>>>(1, (const float*)0, x_q, (float*)0);

    gn_reduce2<<<dim3(64, 8, 1), 256, 0, s0>>>((const float*)0, (const float*)0, 16, 1);
    finalize_stats<<<8, 64, 0, s0>>>(16);
    gn2_apply<<<dim3(512, 8), 256, 0, s0>>>(16, n2_w, n2_b);
    gemm_wmma<<<dim3(32, 8, 8), 256, SMEM4, s0>>>(2, fc1_b, (const float*)0, (float*)0);
    gemm_wmma<<<dim3(32, 2, 8), 256, SMEM4, s0>>>(3, fc2_b, (const float*)0, (float*)d_out);
}

// round 16
// speedup vs baseline: 1.2235x; 1.2235x over previous
#include <cuda_runtime.h>
#include <cuda_bf16.h>
#include <cuda_pipeline.h>
#include <mma.h>
#include <math.h>

using namespace nvcuda;

#define B_   8
#define C_   256
#define P_   4096
#define CP_  1048576
#define KC_  4608
#define STAGE_E 12288   /* split-GEMM stage: bf16 elements (24KB) */
#define STG_B   6144    /* bf16-GEMM stage: bf16 elements (12KB)  */

/* ---------------- scratch (static device globals; no allocs) ------------- */
__device__ float          g_qf [B_*CP_];
__device__ __nv_bfloat16  g_qh [B_*CP_];
__device__ __nv_bfloat16  g_ql [B_*CP_];
__device__ __nv_bfloat16  g_kvh[B_*CP_];
__device__ __nv_bfloat16  g_kvl[B_*CP_];
__device__ float          g_t1 [B_*CP_];
__device__ float          g_off[B_*2*P_];
__device__ __nv_bfloat16  g_sph[B_*CP_];
__device__ float          g_x1 [B_*CP_];
__device__ __nv_bfloat16  g_hnh[B_*CP_];
__device__ __nv_bfloat16  g_h1h[B_*P_*1024];
__device__ __nv_bfloat16  g_wrh[C_*KC_];
__device__ __nv_bfloat16  g_wrl[C_*KC_];
__device__ __nv_bfloat16  g_f1h[1024*C_];
__device__ __nv_bfloat16  g_f2h[C_*1024];
__device__ __nv_bfloat16  g_wch[C_*C_];
__device__ float          g_bc [C_];
__device__ double         g_ps [24][64];
__device__ double         g_pq [24][64];
__device__ float          g_mean[24];
__device__ float          g_rstd[24];
__device__ const int g_tap[9] = {0, 1, 2, 16, 17, 18, 32, 33, 34};

__device__ __forceinline__ void split2(float a, __nv_bfloat16* h, __nv_bfloat16* l) {
    __nv_bfloat16 hh = __float2bfloat16(a);
    *h = hh;
    *l = __float2bfloat16(a - __bfloat162float(hh));
}

/* ------------------------------- GN stats -------------------------------- */
__global__ void gn_reduce2(const float* xa, const float* xb, int so, int use_x1) {
    int b = blockIdx.y, z = blockIdx.z;
    const float* src = (use_x1 != 0) ? (const float*)g_x1 : (z == 0 ? xa : xb);
    const float* xp = src + (size_t)b * CP_;
    double s = 0.0, s2 = 0.0;
    for (int i = blockIdx.x * blockDim.x + threadIdx.x; i < CP_;
         i += gridDim.x * blockDim.x) {
        float v = xp[i];
        s += (double)v; s2 += (double)v * (double)v;
    }
    __shared__ double sh[256];
    __shared__ double sh2[256];
    int t = threadIdx.x;
    sh[t] = s; sh2[t] = s2;
    __syncthreads();
    for (int o = 128; o > 0; o >>= 1) {
        if (t < o) { sh[t] += sh[t + o]; sh2[t] += sh2[t + o]; }
        __syncthreads();
    }
    if (t == 0) {
        int slot = so + z * 8 + b;
        g_ps[slot][blockIdx.x] = sh[0];
        g_pq[slot][blockIdx.x] = sh2[0];
    }
}

__global__ void finalize_stats(int s0) {
    int slot = s0 + blockIdx.x;
    int t = threadIdx.x;
    __shared__ double sh[64];
    __shared__ double sh2[64];
    sh[t] = g_ps[slot][t];
    sh2[t] = g_pq[slot][t];
    __syncthreads();
    for (int o = 32; o > 0; o >>= 1) {
        if (t < o) { sh[t] += sh[t + o]; sh2[t] += sh2[t + o]; }
        __syncthreads();
    }
    if (t == 0) {
        double mu  = sh[0] / (double)CP_;
        double var = sh2[0] / (double)CP_ - mu * mu;
        g_mean[slot] = (float)mu;
        g_rstd[slot] = rsqrtf((float)var + 1e-5f);
    }
}

/* -- GN apply + NCHW->NHWC transpose + split, BOTH tensors in one launch -- */
__global__ void gn_apply_fused(const float* xq, const float* xkv,
                               const float* w, const float* bb) {
    __shared__ float t[32][33];
    int z = blockIdx.z;
    int b = z & 7, which = z >> 3;
    const float* x = which ? xkv : xq;
    float m = g_mean[which * 8 + b], rs = g_rstd[which * 8 + b];
    int p0 = blockIdx.x * 32, c0 = blockIdx.y * 32;
    int tx = threadIdx.x, ty = threadIdx.y;
    const float* xb = x + (size_t)b * CP_;
    for (int i = ty; i < 32; i += 8) {
        int c = c0 + i;
        t[i][tx] = (xb[(size_t)c * P_ + p0 + tx] - m) * rs * w[c] + bb[c];
    }
    __syncthreads();
    size_t ob = (size_t)b * CP_;
    for (int i = ty; i < 32; i += 8) {
        float v = t[tx][i];
        size_t o = ob + (size_t)(p0 + i) * C_ + c0 + tx;
        if (which == 0) {
            g_qf[o] = v;
            split2(v, &g_qh[o], &g_ql[o]);
        } else {
            split2(v, &g_kvh[o], &g_kvl[o]);
        }
    }
}

/* --------- GN2 apply: bf16-rounded output only (fc path is 1-MMA) -------- */
__global__ void gn2_apply(int so, const float* w, const float* bb) {
    int b = blockIdx.y;
    float m = g_mean[so + b], rs = g_rstd[so + b];
    const float* xb = g_x1 + (size_t)b * CP_;
    size_t ob = (size_t)b * CP_;
    for (int i = blockIdx.x * blockDim.x + threadIdx.x; i < CP_;
         i += gridDim.x * blockDim.x) {
        int c = i & 255;
        float v = (xb[i] - m) * rs * w[c] + bb[c];
        g_hnh[ob + i] = __float2bfloat16(v);
    }
}

/* --------------------------- weight preparation -------------------------- */
__global__ void prep_split(const float* src, int n, int wsel) {
    int i = blockIdx.x * blockDim.x + threadIdx.x;
    if (i < n) {
        if (wsel == 1) g_f1h[i] = __float2bfloat16(src[i]);
        else           g_f2h[i] = __float2bfloat16(src[i]);
    }
}

__global__ void prep_conv_w(const float* src) {
    int i = blockIdx.x * blockDim.x + threadIdx.x;
    if (i < C_ * KC_) {
        int o = i / KC_, k = i - o * KC_;
        int tap = k >> 9, cc = k & 511;
        float v = src[(size_t)o * KC_ + (size_t)cc * 9 + tap];
        split2(v, &g_wrh[i], &g_wrl[i]);
    }
}

__global__ void combine_w(const float* pw, const float* pb,
                          const float* kw, const float* kb) {
    int idx = blockIdx.x * blockDim.x + threadIdx.x;
    if (idx < 65536) {
        int o = idx >> 8, c = idx & 255;
        float s = 0.f;
        for (int j = 0; j < 256; j++)
            s += pw[o * 256 + j] * kw[(256 + j) * 256 + c];
        g_wch[idx] = __float2bfloat16(s);
    } else if (idx < 65536 + 256) {
        int o = idx - 65536;
        float s = pb[o];
        for (int j = 0; j < 256; j++)
            s += pw[o * 256 + j] * kb[256 + j];
        g_bc[o] = s;
    }
}

/* ======= pure-bf16 wmma GEMM (fc1/fc2/v), CTA 128x128, 4-stage =========== */
/* cfg 1: v-GEMM  A=g_sph K=256,  B=g_wch, bias=g_bc, +x_q NCHW -> g_x1     */
/* cfg 2: fc1     A=g_hnh K=256,  B=g_f1h N=1024, gelu -> g_h1h             */
/* cfg 3: fc2     A=g_h1h K=1024, B=g_f2h, +g_x1 res -> out_ext NCHW        */
__global__ __launch_bounds__(256, 2)
void gemm_bf16(int cfg, const float* bias_ext, const float* res_ext, float* out_ext) {
    extern __shared__ __align__(32) char smd[];
    __nv_bfloat16* base = (__nv_bfloat16*)smd;
    float* stP = (float*)smd;

    int K = (cfg == 3) ? 1024 : 256;
    int N = (cfg == 2) ? 1024 : 256;
    const __nv_bfloat16* Ah;
    const __nv_bfloat16* Bh;
    const float* bias;
    if (cfg == 1)      { Ah = g_sph; Bh = g_wch; bias = g_bc; }
    else if (cfg == 2) { Ah = g_hnh; Bh = g_f1h; bias = bias_ext; }
    else               { Ah = g_h1h; Bh = g_f2h; bias = bias_ext; }

    int tid = threadIdx.x, lane = tid & 31, wrp = tid >> 5;
    int wm = (wrp >> 2) * 64, wn = (wrp & 3) * 32;
    int b  = blockIdx.z;
    int m0 = blockIdx.x * 128, n0 = blockIdx.y * 128;
    size_t asb = (size_t)P_ * K;
    const __nv_bfloat16* Ahb = Ah + (size_t)b * asb;

    wmma::fragment<wmma::accumulator, 16, 16, 16, float> acc[4][2];
    for (int i = 0; i < 4; i++)
        for (int j = 0; j < 2; j++)
            wmma::fill_fragment(acc[i][j], 0.0f);

    int row = tid >> 1, c8 = (tid & 1) * 8;
    size_t aoff = (size_t)(m0 + row) * K + c8;
    size_t boff = (size_t)(n0 + row) * K + c8;
    int nk = K >> 4;
    int sidx = row * 24 + c8;

    for (int p = 0; p < 3 && p < nk; p++) {
        __nv_bfloat16* sg = base + p * STG_B;
        int ko = p << 4;
        __pipeline_memcpy_async(sg + sidx,        Ahb + aoff + ko, 16);
        __pipeline_memcpy_async(sg + 3072 + sidx, Bh + boff + ko, 16);
        __pipeline_commit();
    }

    for (int ks = 0;; ks++) {
        __pipeline_wait_prior(2);
        __syncthreads();
        __nv_bfloat16* sg = base + (ks & 3) * STG_B;
        wmma::fragment<wmma::matrix_b, 16, 16, 16, __nv_bfloat16, wmma::col_major> fbh0, fbh1;
        wmma::load_matrix_sync(fbh0, sg + 3072 + wn * 24, 24);
        wmma::load_matrix_sync(fbh1, sg + 3072 + (wn + 16) * 24, 24);
        for (int i = 0; i < 4; i++) {
            wmma::fragment<wmma::matrix_a, 16, 16, 16, __nv_bfloat16, wmma::row_major> fah;
            wmma::load_matrix_sync(fah, sg + (wm + i * 16) * 24, 24);
            wmma::mma_sync(acc[i][0], fah, fbh0, acc[i][0]);
            wmma::mma_sync(acc[i][1], fah, fbh1, acc[i][1]);
        }
        if (ks + 1 >= nk) break;
        if (ks + 3 < nk) {
            __nv_bfloat16* sn = base + ((ks + 3) & 3) * STG_B;
            int ko = (ks + 3) << 4;
            __pipeline_memcpy_async(sn + sidx,        Ahb + aoff + ko, 16);
            __pipeline_memcpy_async(sn + 3072 + sidx, Bh + boff + ko, 16);
        }
        __pipeline_commit();
    }

    __pipeline_wait_prior(0);
    __syncthreads();

    int r2 = lane >> 1, cB = (lane & 1) * 8;
    float* stw = stP + wrp * 320;
    for (int i = 0; i < 4; i++) {
        for (int j = 0; j < 2; j++) {
            wmma::store_matrix_sync(stw, acc[i][j], 20, wmma::mem_row_major);
            __syncwarp();
            int m = m0 + wm + i * 16 + r2;
            int n = n0 + wn + j * 16 + cB;
            for (int c = 0; c < 8; c++) {
                float v = stw[r2 * 20 + cB + c] + bias[n + c];
                if (cfg == 1) {
                    v += res_ext[(size_t)b * CP_ + (size_t)(n + c) * P_ + m];
                    g_x1[(size_t)b * CP_ + (size_t)m * C_ + n + c] = v;
                } else if (cfg == 2) {
                    v = 0.5f * v * (1.0f + erff(v * 0.70710678118654752f));
                    size_t o = (size_t)b * (size_t)P_ * N + (size_t)m * N + n + c;
                    g_h1h[o] = __float2bfloat16(v);
                } else {
                    v += g_x1[(size_t)b * CP_ + (size_t)m * C_ + n + c];
                    out_ext[(size_t)b * CP_ + (size_t)(n + c) * P_ + m] = v;
                }
            }
            __syncwarp();
        }
    }
}

/* ---- conv3x3 implicit GEMM: split-bf16 3-MMA (offset path), 4-stage ----- */
__device__ __forceinline__ void conv_issue_slab(
    int kn, __nv_bfloat16* sg, int sidx, int ph, int pw, int c8,
    size_t bbase, size_t boff) {
    int tap = kn >> 9, cc = (kn & 511) + c8;
    int e = g_tap[tap];
    int hh = ph + (e >> 4) - 1, ww = pw + (e & 15) - 1;
    if (hh >= 0 && hh < 64 && ww >= 0 && ww < 64) {
        size_t base = bbase + (size_t)((hh << 6) + ww) * C_;
        if (cc < 256) {
            __pipeline_memcpy_async(sg + sidx,        g_kvh + base + cc, 16);
            __pipeline_memcpy_async(sg + 3072 + sidx, g_kvl + base + cc, 16);
        } else {
            __pipeline_memcpy_async(sg + sidx,        g_qh + base + cc - 256, 16);
            __pipeline_memcpy_async(sg + 3072 + sidx, g_ql + base + cc - 256, 16);
        }
    } else {
        __pipeline_memcpy_async(sg + sidx,        g_kvh, 16, 16);
        __pipeline_memcpy_async(sg + 3072 + sidx, g_kvl, 16, 16);
    }
    __pipeline_memcpy_async(sg + 6144 + sidx, g_wrh + boff + kn, 16);
    __pipeline_memcpy_async(sg + 9216 + sidx, g_wrl + boff + kn, 16);
}

__global__ __launch_bounds__(256, 2)
void conv_wmma(const float* bias) {
    extern __shared__ __align__(32) char smd[];
    __nv_bfloat16* base = (__nv_bfloat16*)smd;
    float* stP = (float*)smd;

    int tid = threadIdx.x, lane = tid & 31, wrp = tid >> 5;
    int wm = (wrp >> 2) * 64, wn = (wrp & 3) * 32;
    int b  = blockIdx.z;
    int m0 = blockIdx.x * 128, n0 = blockIdx.y * 128;

    wmma::fragment<wmma::accumulator, 16, 16, 16, float> acc[4][2];
    for (int i = 0; i < 4; i++)
        for (int j = 0; j < 2; j++)
            wmma::fill_fragment(acc[i][j], 0.0f);

    int row = tid >> 1, c8 = (tid & 1) * 8;
    int pix = m0 + row, ph = pix >> 6, pw = pix & 63;
    size_t bbase = (size_t)b * CP_;
    size_t boff = (size_t)(n0 + row) * KC_ + c8;
    const int nk = KC_ >> 4;
    int sidx = row * 24 + c8;

    for (int p = 0; p < 3; p++) {
        conv_issue_slab(p << 4, base + p * STAGE_E, sidx, ph, pw, c8, bbase, boff);
        __pipeline_commit();
    }

    for (int ks = 0;; ks++) {
        __pipeline_wait_prior(2);
        __syncthreads();
        __nv_bfloat16* sg = base + (ks & 3) * STAGE_E;
        wmma::fragment<wmma::matrix_b, 16, 16, 16, __nv_bfloat16, wmma::col_major> fbh0, fbh1, fbl0, fbl1;
        wmma::load_matrix_sync(fbh0, sg + 6144 + wn * 24, 24);
        wmma::load_matrix_sync(fbh1, sg + 6144 + (wn + 16) * 24, 24);
        wmma::load_matrix_sync(fbl0, sg + 9216 + wn * 24, 24);
        wmma::load_matrix_sync(fbl1, sg + 9216 + (wn + 16) * 24, 24);
        for (int i = 0; i < 4; i++) {
            wmma::fragment<wmma::matrix_a, 16, 16, 16, __nv_bfloat16, wmma::row_major> fah, fal;
            wmma::load_matrix_sync(fah, sg + (wm + i * 16) * 24, 24);
            wmma::load_matrix_sync(fal, sg + 3072 + (wm + i * 16) * 24, 24);
            wmma::mma_sync(acc[i][0], fah, fbh0, acc[i][0]);
            wmma::mma_sync(acc[i][0], fah, fbl0, acc[i][0]);
            wmma::mma_sync(acc[i][0], fal, fbh0, acc[i][0]);
            wmma::mma_sync(acc[i][1], fah, fbh1, acc[i][1]);
            wmma::mma_sync(acc[i][1], fah, fbl1, acc[i][1]);
            wmma::mma_sync(acc[i][1], fal, fbh1, acc[i][1]);
        }
        if (ks + 1 >= nk) break;
        if (ks + 3 < nk)
            conv_issue_slab((ks + 3) << 4, base + ((ks + 3) & 3) * STAGE_E,
                            sidx, ph, pw, c8, bbase, boff);
        __pipeline_commit();
    }

    __pipeline_wait_prior(0);
    __syncthreads();

    int r2 = lane >> 1, cB = (lane & 1) * 8;
    float* stw = stP + wrp * 320;
    for (int i = 0; i < 4; i++) {
        for (int j = 0; j < 2; j++) {
            wmma::store_matrix_sync(stw, acc[i][j], 20, wmma::mem_row_major);
            __syncwarp();
            int m = m0 + wm + i * 16 + r2;
            int n = n0 + wn + j * 16 + cB;
            for (int c = 0; c < 8; c++) {
                float v = stw[r2 * 20 + cB + c] + bias[n + c];
                g_t1[bbase + (size_t)m * C_ + n + c] = fmaxf(v, 0.f);
            }
            __syncwarp();
        }
    }
}

/* --------------------- offset head: 256 -> 2 (NHWC) ---------------------- */
__global__ void off_kernel(const float* w2, const float* b2) {
    int gid = blockIdx.x * blockDim.x + threadIdx.x;
    int pix = gid >> 5, lane = gid & 31;
    int b = pix >> 12, p = pix & 4095;
    const float* t = g_t1 + (size_t)b * CP_ + (size_t)p * C_;
    float s0 = 0.f, s1 = 0.f;
    for (int c0 = 0; c0 < 256; c0 += 32) {
        float v = t[c0 + lane];
        s0 += w2[c0 + lane] * v;
        s1 += w2[256 + c0 + lane] * v;
    }
    for (int o = 16; o > 0; o >>= 1) {
        s0 += __shfl_xor_sync(0xffffffffu, s0, o);
        s1 += __shfl_xor_sync(0xffffffffu, s1, o);
    }
    if (lane == 0) {
        g_off[b * 2 * P_ + p]      = s0 + b2[0];
        g_off[b * 2 * P_ + P_ + p] = s1 + b2[1];
    }
}

/* ----- bilinear grid-sample (zeros pad), NHWC, bf16-rounded output ------- */
__global__ void sample_kernel() {
    int gid = blockIdx.x * blockDim.x + threadIdx.x;
    int pix = gid >> 5, lane = gid & 31;
    int b = pix >> 12, p = pix & 4095;
    float ox = g_off[b * 2 * P_ + p];
    float oy = g_off[b * 2 * P_ + P_ + p];
    float gx = ox / 63.0f * 2.0f - 1.0f;
    float gy = oy / 63.0f * 2.0f - 1.0f;
    float ix = (gx + 1.0f) * 0.5f * 63.0f;
    float iy = (gy + 1.0f) * 0.5f * 63.0f;
    float x0f = floorf(ix), y0f = floorf(iy);
    float wx1 = ix - x0f, wx0 = 1.0f - wx1;
    float wy1 = iy - y0f, wy0 = 1.0f - wy1;
    int x0 = (int)x0f,          y0 = (int)y0f;
    int x1 = (int)(x0f + 1.0f), y1 = (int)(y0f + 1.0f);
    bool vx0 = (x0 >= 0 && x0 < 64), vx1 = (x1 >= 0 && x1 < 64);
    bool vy0 = (y0 >= 0 && y0 < 64), vy1 = (y1 >= 0 && y1 < 64);
    float e00 = (vy0 && vx0) ? wy0 * wx0 : 0.f;
    float e01 = (vy0 && vx1) ? wy0 * wx1 : 0.f;
    float e10 = (vy1 && vx0) ? wy1 * wx0 : 0.f;
    float e11 = (vy1 && vx1) ? wy1 * wx1 : 0.f;
    int xc0 = min(max(x0, 0), 63), xc1 = min(max(x1, 0), 63);
    int yc0 = min(max(y0, 0), 63), yc1 = min(max(y1, 0), 63);
    const float* base = g_qf + (size_t)b * CP_;
    const float* p00 = base + (size_t)((yc0 << 6) + xc0) * C_;
    const float* p01 = base + (size_t)((yc0 << 6) + xc1) * C_;
    const float* p10 = base + (size_t)((yc1 << 6) + xc0) * C_;
    const float* p11 = base + (size_t)((yc1 << 6) + xc1) * C_;
    size_t o = (size_t)b * CP_ + (size_t)p * C_;
    for (int c = lane; c < C_; c += 32) {
        float v = e00 * p00[c] + e01 * p01[c] + e10 * p10[c] + e11 * p11[c];
        g_sph[o + c] = __float2bfloat16(v);
    }
}

/* ------------------------------ launch ----------------------------------- */
extern "C" void kernel_launch(void* const* d_in, const int* in_sizes, int n_in,
                              void* d_out, int out_size) {
    const float* x_q    = (const float*)d_in[0];
    const float* x_kv   = (const float*)d_in[1];
    const float* n1_w   = (const float*)d_in[2];
    const float* n1_b   = (const float*)d_in[3];
    const float* kv_w   = (const float*)d_in[6];
    const float* kv_b   = (const float*)d_in[7];
    const float* off1_w = (const float*)d_in[8];
    const float* off1_b = (const float*)d_in[9];
    const float* off2_w = (const float*)d_in[10];
    const float* off2_b = (const float*)d_in[11];
    const float* proj_w = (const float*)d_in[12];
    const float* proj_b = (const float*)d_in[13];
    const float* n2_w   = (const float*)d_in[14];
    const float* n2_b   = (const float*)d_in[15];
    const float* fc1_w  = (const float*)d_in[16];
    const float* fc1_b  = (const float*)d_in[17];
    const float* fc2_w  = (const float*)d_in[18];
    const float* fc2_b  = (const float*)d_in[19];

    const int SMEM4  = 4 * 24576;   /* conv: 96KB dynamic */
    const int SMEM4B = 4 * 12288;   /* bf16 gemm: 48KB dynamic */
    static int attr_done = 0;
    if (!attr_done) {
        cudaFuncSetAttribute(conv_wmma, cudaFuncAttributeMaxDynamicSharedMemorySize, SMEM4);
        cudaFuncSetAttribute(gemm_bf16, cudaFuncAttributeMaxDynamicSharedMemorySize, SMEM4B);
        attr_done = 1;
    }

    cudaStream_t s0 = 0;
    static cudaStream_t s1 = 0;
    if (!s1) cudaStreamCreateWithFlags(&s1, cudaStreamNonBlocking);
    static cudaEvent_t evFork = 0, evPrep = 0;
    if (!evFork) {
        cudaEventCreateWithFlags(&evFork, cudaEventDisableTiming);
        cudaEventCreateWithFlags(&evPrep, cudaEventDisableTiming);
    }

    cudaEventRecord(evFork, s0);
    cudaStreamWaitEvent(s1, evFork, 0);
    prep_conv_w<<<(C_ * KC_ + 255) / 256, 256, 0, s1>>>(off1_w);
    prep_split<<<(1024 * C_ + 255) / 256, 256, 0, s1>>>(fc1_w, 1024 * C_, 1);
    prep_split<<<(C_ * 1024 + 255) / 256, 256, 0, s1>>>(fc2_w, C_ * 1024, 2);
    combine_w<<<(65536 + 256 + 255) / 256, 256, 0, s1>>>(proj_w, proj_b, kv_w, kv_b);
    cudaEventRecord(evPrep, s1);

    gn_reduce2<<<dim3(64, 8, 2), 256, 0, s0>>>(x_q, x_kv, 0, 0);
    finalize_stats<<<16, 64, 0, s0>>>(0);
    gn_apply_fused<<<dim3(128, 8, 16), dim3(32, 8), 0, s0>>>(x_q, x_kv, n1_w, n1_b);
    cudaStreamWaitEvent(s0, evPrep, 0);
    conv_wmma<<<dim3(32, 2, 8), 256, SMEM4, s0>>>(off1_b);
    off_kernel<<<(B_ * P_ * 32) / 256, 256, 0, s0>>>(off2_w, off2_b);
    sample_kernel<<<(B_ * P_ * 32) / 256, 256, 0, s0>>>();
    gemm_bf16<<<dim3(32, 2, 8), 256, SMEM4B, s0>>>(1, (const float*)0, x_q, (float*)0);

    gn_reduce2<<<dim3(64, 8, 1), 256, 0, s0>>>((const float*)0, (const float*)0, 16, 1);
    finalize_stats<<<8, 64, 0, s0>>>(16);
    gn2_apply<<<dim3(512, 8), 256, 0, s0>>>(16, n2_w, n2_b);
    gemm_bf16<<<dim3(32, 8, 8), 256, SMEM4B, s0>>>(2, fc1_b, (const float*)0, (float*)0);
    gemm_bf16<<<dim3(32, 2, 8), 256, SMEM4B, s0>>>(3, fc2_b, (const float*)0, (float*)d_out);
}

// round 17
// speedup vs baseline: 1.2253x; 1.0015x over previous
#include <cuda_runtime.h>
#include <cuda_bf16.h>
#include <cuda_pipeline.h>
#include <mma.h>
#include <math.h>

using namespace nvcuda;

#define B_   8
#define C_   256
#define P_   4096
#define CP_  1048576
#define KC_  4608
#define STAGE_E 12288   /* split-GEMM stage: bf16 elements (24KB) */
#define STG_B   6144    /* bf16-GEMM stage: bf16 elements (12KB)  */

/* ---------------- scratch (static device globals; no allocs) ------------- */
__device__ float          g_qf [B_*CP_];
__device__ __nv_bfloat16  g_qh [B_*CP_];
__device__ __nv_bfloat16  g_ql [B_*CP_];
__device__ __nv_bfloat16  g_kvh[B_*CP_];
__device__ __nv_bfloat16  g_kvl[B_*CP_];
__device__ float          g_off[B_*2*P_];
__device__ __nv_bfloat16  g_sph[B_*CP_];
__device__ float          g_x1 [B_*CP_];
__device__ __nv_bfloat16  g_hnh[B_*CP_];
__device__ __nv_bfloat16  g_h1h[B_*P_*1024];
__device__ __nv_bfloat16  g_wrh[C_*KC_];
__device__ __nv_bfloat16  g_wrl[C_*KC_];
__device__ __nv_bfloat16  g_f1h[1024*C_];
__device__ __nv_bfloat16  g_f2h[C_*1024];
__device__ __nv_bfloat16  g_wch[C_*C_];
__device__ float          g_bc [C_];
__device__ double         g_ps [24][64];
__device__ double         g_pq [24][64];
__device__ float          g_mean[24];
__device__ float          g_rstd[24];
__device__ const int g_tap[9] = {0, 1, 2, 16, 17, 18, 32, 33, 34};

__device__ __forceinline__ void split2(float a, __nv_bfloat16* h, __nv_bfloat16* l) {
    __nv_bfloat16 hh = __float2bfloat16(a);
    *h = hh;
    *l = __float2bfloat16(a - __bfloat162float(hh));
}

/* ------------------------------- GN stats -------------------------------- */
__global__ void gn_reduce2(const float* xa, const float* xb, int so, int use_x1) {
    int b = blockIdx.y, z = blockIdx.z;
    const float* src = (use_x1 != 0) ? (const float*)g_x1 : (z == 0 ? xa : xb);
    const float* xp = src + (size_t)b * CP_;
    double s = 0.0, s2 = 0.0;
    for (int i = blockIdx.x * blockDim.x + threadIdx.x; i < CP_;
         i += gridDim.x * blockDim.x) {
        float v = xp[i];
        s += (double)v; s2 += (double)v * (double)v;
    }
    __shared__ double sh[256];
    __shared__ double sh2[256];
    int t = threadIdx.x;
    sh[t] = s; sh2[t] = s2;
    __syncthreads();
    for (int o = 128; o > 0; o >>= 1) {
        if (t < o) { sh[t] += sh[t + o]; sh2[t] += sh2[t + o]; }
        __syncthreads();
    }
    if (t == 0) {
        int slot = so + z * 8 + b;
        g_ps[slot][blockIdx.x] = sh[0];
        g_pq[slot][blockIdx.x] = sh2[0];
    }
}

__global__ void finalize_stats(int s0) {
    int slot = s0 + blockIdx.x;
    int t = threadIdx.x;
    __shared__ double sh[64];
    __shared__ double sh2[64];
    sh[t] = g_ps[slot][t];
    sh2[t] = g_pq[slot][t];
    __syncthreads();
    for (int o = 32; o > 0; o >>= 1) {
        if (t < o) { sh[t] += sh[t + o]; sh2[t] += sh2[t + o]; }
        __syncthreads();
    }
    if (t == 0) {
        double mu  = sh[0] / (double)CP_;
        double var = sh2[0] / (double)CP_ - mu * mu;
        g_mean[slot] = (float)mu;
        g_rstd[slot] = rsqrtf((float)var + 1e-5f);
    }
}

/* -- GN apply + NCHW->NHWC transpose + split, BOTH tensors in one launch -- */
__global__ void gn_apply_fused(const float* xq, const float* xkv,
                               const float* w, const float* bb) {
    __shared__ float t[32][33];
    int z = blockIdx.z;
    int b = z & 7, which = z >> 3;
    const float* x = which ? xkv : xq;
    float m = g_mean[which * 8 + b], rs = g_rstd[which * 8 + b];
    int p0 = blockIdx.x * 32, c0 = blockIdx.y * 32;
    int tx = threadIdx.x, ty = threadIdx.y;
    const float* xb = x + (size_t)b * CP_;
    for (int i = ty; i < 32; i += 8) {
        int c = c0 + i;
        t[i][tx] = (xb[(size_t)c * P_ + p0 + tx] - m) * rs * w[c] + bb[c];
    }
    __syncthreads();
    size_t ob = (size_t)b * CP_;
    for (int i = ty; i < 32; i += 8) {
        float v = t[tx][i];
        size_t o = ob + (size_t)(p0 + i) * C_ + c0 + tx;
        if (which == 0) {
            g_qf[o] = v;
            split2(v, &g_qh[o], &g_ql[o]);
        } else {
            split2(v, &g_kvh[o], &g_kvl[o]);
        }
    }
}

/* --------- GN2 apply: bf16-rounded output only (fc path is 1-MMA) -------- */
__global__ void gn2_apply(int so, const float* w, const float* bb) {
    int b = blockIdx.y;
    float m = g_mean[so + b], rs = g_rstd[so + b];
    const float* xb = g_x1 + (size_t)b * CP_;
    size_t ob = (size_t)b * CP_;
    for (int i = blockIdx.x * blockDim.x + threadIdx.x; i < CP_;
         i += gridDim.x * blockDim.x) {
        int c = i & 255;
        float v = (xb[i] - m) * rs * w[c] + bb[c];
        g_hnh[ob + i] = __float2bfloat16(v);
    }
}

/* --------------------------- weight preparation -------------------------- */
__global__ void prep_split(const float* src, int n, int wsel) {
    int i = blockIdx.x * blockDim.x + threadIdx.x;
    if (i < n) {
        if (wsel == 1) g_f1h[i] = __float2bfloat16(src[i]);
        else           g_f2h[i] = __float2bfloat16(src[i]);
    }
}

__global__ void prep_conv_w(const float* src) {
    int i = blockIdx.x * blockDim.x + threadIdx.x;
    if (i < C_ * KC_) {
        int o = i / KC_, k = i - o * KC_;
        int tap = k >> 9, cc = k & 511;
        float v = src[(size_t)o * KC_ + (size_t)cc * 9 + tap];
        split2(v, &g_wrh[i], &g_wrl[i]);
    }
}

/* tiled 256x256x256 fp32 GEMM: g_wch = bf16(proj_w @ kv_w[v half]) */
__global__ void combine_w_t(const float* pw, const float* kw) {
    __shared__ float As[16][16];
    __shared__ float Bs[16][17];
    int tx = threadIdx.x, ty = threadIdx.y;
    int o = blockIdx.y * 16 + ty, c = blockIdx.x * 16 + tx;
    float s = 0.f;
    for (int k0 = 0; k0 < 256; k0 += 16) {
        As[ty][tx] = pw[o * 256 + k0 + tx];
        Bs[ty][tx] = kw[(256 + k0 + ty) * 256 + c];
        __syncthreads();
        for (int k = 0; k < 16; k++) s += As[ty][k] * Bs[k][tx];
        __syncthreads();
    }
    g_wch[o * 256 + c] = __float2bfloat16(s);
}

__global__ void combine_b(const float* pw, const float* pb, const float* kb) {
    int o = threadIdx.x;
    if (o < 256) {
        float s = pb[o];
        for (int j = 0; j < 256; j++)
            s += pw[o * 256 + j] * kb[256 + j];
        g_bc[o] = s;
    }
}

/* init g_off with offset bias (conv epilogue atomically accumulates) */
__global__ void init_off(const float* b2) {
    int idx = blockIdx.x * blockDim.x + threadIdx.x;   /* B*2*P */
    if (idx < B_ * 2 * P_)
        g_off[idx] = b2[(idx >> 12) & 1];
}

/* ======= pure-bf16 wmma GEMM (fc1/fc2/v), CTA 128x128, 4-stage =========== */
/* cfg 1: v-GEMM  A=g_sph K=256,  B=g_wch, bias=g_bc, +x_q NCHW -> g_x1     */
/* cfg 2: fc1     A=g_hnh K=256,  B=g_f1h N=1024, gelu -> g_h1h             */
/* cfg 3: fc2     A=g_h1h K=1024, B=g_f2h, +g_x1 res -> out_ext NCHW        */
__global__ __launch_bounds__(256, 2)
void gemm_bf16(int cfg, const float* bias_ext, const float* res_ext, float* out_ext) {
    extern __shared__ __align__(32) char smd[];
    __nv_bfloat16* base = (__nv_bfloat16*)smd;
    float* stP = (float*)smd;

    int K = (cfg == 3) ? 1024 : 256;
    int N = (cfg == 2) ? 1024 : 256;
    const __nv_bfloat16* Ah;
    const __nv_bfloat16* Bh;
    const float* bias;
    if (cfg == 1)      { Ah = g_sph; Bh = g_wch; bias = g_bc; }
    else if (cfg == 2) { Ah = g_hnh; Bh = g_f1h; bias = bias_ext; }
    else               { Ah = g_h1h; Bh = g_f2h; bias = bias_ext; }

    int tid = threadIdx.x, lane = tid & 31, wrp = tid >> 5;
    int wm = (wrp >> 2) * 64, wn = (wrp & 3) * 32;
    int b  = blockIdx.z;
    int m0 = blockIdx.x * 128, n0 = blockIdx.y * 128;
    size_t asb = (size_t)P_ * K;
    const __nv_bfloat16* Ahb = Ah + (size_t)b * asb;

    wmma::fragment<wmma::accumulator, 16, 16, 16, float> acc[4][2];
    for (int i = 0; i < 4; i++)
        for (int j = 0; j < 2; j++)
            wmma::fill_fragment(acc[i][j], 0.0f);

    int row = tid >> 1, c8 = (tid & 1) * 8;
    size_t aoff = (size_t)(m0 + row) * K + c8;
    size_t boff = (size_t)(n0 + row) * K + c8;
    int nk = K >> 4;
    int sidx = row * 24 + c8;

    for (int p = 0; p < 3 && p < nk; p++) {
        __nv_bfloat16* sg = base + p * STG_B;
        int ko = p << 4;
        __pipeline_memcpy_async(sg + sidx,        Ahb + aoff + ko, 16);
        __pipeline_memcpy_async(sg + 3072 + sidx, Bh + boff + ko, 16);
        __pipeline_commit();
    }

    for (int ks = 0;; ks++) {
        __pipeline_wait_prior(2);
        __syncthreads();
        __nv_bfloat16* sg = base + (ks & 3) * STG_B;
        wmma::fragment<wmma::matrix_b, 16, 16, 16, __nv_bfloat16, wmma::col_major> fbh0, fbh1;
        wmma::load_matrix_sync(fbh0, sg + 3072 + wn * 24, 24);
        wmma::load_matrix_sync(fbh1, sg + 3072 + (wn + 16) * 24, 24);
        for (int i = 0; i < 4; i++) {
            wmma::fragment<wmma::matrix_a, 16, 16, 16, __nv_bfloat16, wmma::row_major> fah;
            wmma::load_matrix_sync(fah, sg + (wm + i * 16) * 24, 24);
            wmma::mma_sync(acc[i][0], fah, fbh0, acc[i][0]);
            wmma::mma_sync(acc[i][1], fah, fbh1, acc[i][1]);
        }
        if (ks + 1 >= nk) break;
        if (ks + 3 < nk) {
            __nv_bfloat16* sn = base + ((ks + 3) & 3) * STG_B;
            int ko = (ks + 3) << 4;
            __pipeline_memcpy_async(sn + sidx,        Ahb + aoff + ko, 16);
            __pipeline_memcpy_async(sn + 3072 + sidx, Bh + boff + ko, 16);
        }
        __pipeline_commit();
    }

    __pipeline_wait_prior(0);
    __syncthreads();

    int r2 = lane >> 1, cB = (lane & 1) * 8;
    float* stw = stP + wrp * 320;
    for (int i = 0; i < 4; i++) {
        for (int j = 0; j < 2; j++) {
            wmma::store_matrix_sync(stw, acc[i][j], 20, wmma::mem_row_major);
            __syncwarp();
            int m = m0 + wm + i * 16 + r2;
            int n = n0 + wn + j * 16 + cB;
            for (int c = 0; c < 8; c++) {
                float v = stw[r2 * 20 + cB + c] + bias[n + c];
                if (cfg == 1) {
                    v += res_ext[(size_t)b * CP_ + (size_t)(n + c) * P_ + m];
                    g_x1[(size_t)b * CP_ + (size_t)m * C_ + n + c] = v;
                } else if (cfg == 2) {
                    v = 0.5f * v * (1.0f + erff(v * 0.70710678118654752f));
                    size_t o = (size_t)b * (size_t)P_ * N + (size_t)m * N + n + c;
                    g_h1h[o] = __float2bfloat16(v);
                } else {
                    v += g_x1[(size_t)b * CP_ + (size_t)m * C_ + n + c];
                    out_ext[(size_t)b * CP_ + (size_t)(n + c) * P_ + m] = v;
                }
            }
            __syncwarp();
        }
    }
}

/* ---- conv3x3 implicit GEMM: split-bf16 3-MMA + FUSED offset head -------- */
/* epilogue: relu(conv+bias), dot with off2_w partials, atomicAdd -> g_off   */
__device__ __forceinline__ void conv_issue_slab(
    int kn, __nv_bfloat16* sg, int sidx, int ph, int pw, int c8,
    size_t bbase, size_t boff) {
    int tap = kn >> 9, cc = (kn & 511) + c8;
    int e = g_tap[tap];
    int hh = ph + (e >> 4) - 1, ww = pw + (e & 15) - 1;
    if (hh >= 0 && hh < 64 && ww >= 0 && ww < 64) {
        size_t base = bbase + (size_t)((hh << 6) + ww) * C_;
        if (cc < 256) {
            __pipeline_memcpy_async(sg + sidx,        g_kvh + base + cc, 16);
            __pipeline_memcpy_async(sg + 3072 + sidx, g_kvl + base + cc, 16);
        } else {
            __pipeline_memcpy_async(sg + sidx,        g_qh + base + cc - 256, 16);
            __pipeline_memcpy_async(sg + 3072 + sidx, g_ql + base + cc - 256, 16);
        }
    } else {
        __pipeline_memcpy_async(sg + sidx,        g_kvh, 16, 16);
        __pipeline_memcpy_async(sg + 3072 + sidx, g_kvl, 16, 16);
    }
    __pipeline_memcpy_async(sg + 6144 + sidx, g_wrh + boff + kn, 16);
    __pipeline_memcpy_async(sg + 9216 + sidx, g_wrl + boff + kn, 16);
}

__global__ __launch_bounds__(256, 2)
void conv_wmma(const float* bias, const float* w2) {
    extern __shared__ __align__(32) char smd[];
    __nv_bfloat16* base = (__nv_bfloat16*)smd;
    float* stP = (float*)smd;

    int tid = threadIdx.x, lane = tid & 31, wrp = tid >> 5;
    int wm = (wrp >> 2) * 64, wn = (wrp & 3) * 32;
    int b  = blockIdx.z;
    int m0 = blockIdx.x * 128, n0 = blockIdx.y * 128;

    wmma::fragment<wmma::accumulator, 16, 16, 16, float> acc[4][2];
    for (int i = 0; i < 4; i++)
        for (int j = 0; j < 2; j++)
            wmma::fill_fragment(acc[i][j], 0.0f);

    int row = tid >> 1, c8 = (tid & 1) * 8;
    int pix = m0 + row, ph = pix >> 6, pw = pix & 63;
    size_t bbase = (size_t)b * CP_;
    size_t boff = (size_t)(n0 + row) * KC_ + c8;
    const int nk = KC_ >> 4;
    int sidx = row * 24 + c8;

    for (int p = 0; p < 3; p++) {
        conv_issue_slab(p << 4, base + p * STAGE_E, sidx, ph, pw, c8, bbase, boff);
        __pipeline_commit();
    }

    for (int ks = 0;; ks++) {
        __pipeline_wait_prior(2);
        __syncthreads();
        __nv_bfloat16* sg = base + (ks & 3) * STAGE_E;
        wmma::fragment<wmma::matrix_b, 16, 16, 16, __nv_bfloat16, wmma::col_major> fbh0, fbh1, fbl0, fbl1;
        wmma::load_matrix_sync(fbh0, sg + 6144 + wn * 24, 24);
        wmma::load_matrix_sync(fbh1, sg + 6144 + (wn + 16) * 24, 24);
        wmma::load_matrix_sync(fbl0, sg + 9216 + wn * 24, 24);
        wmma::load_matrix_sync(fbl1, sg + 9216 + (wn + 16) * 24, 24);
        for (int i = 0; i < 4; i++) {
            wmma::fragment<wmma::matrix_a, 16, 16, 16, __nv_bfloat16, wmma::row_major> fah, fal;
            wmma::load_matrix_sync(fah, sg + (wm + i * 16) * 24, 24);
            wmma::load_matrix_sync(fal, sg + 3072 + (wm + i * 16) * 24, 24);
            wmma::mma_sync(acc[i][0], fah, fbh0, acc[i][0]);
            wmma::mma_sync(acc[i][0], fah, fbl0, acc[i][0]);
            wmma::mma_sync(acc[i][0], fal, fbh0, acc[i][0]);
            wmma::mma_sync(acc[i][1], fah, fbh1, acc[i][1]);
            wmma::mma_sync(acc[i][1], fah, fbl1, acc[i][1]);
            wmma::mma_sync(acc[i][1], fal, fbh1, acc[i][1]);
        }
        if (ks + 1 >= nk) break;
        if (ks + 3 < nk)
            conv_issue_slab((ks + 3) << 4, base + ((ks + 3) & 3) * STAGE_E,
                            sidx, ph, pw, c8, bbase, boff);
        __pipeline_commit();
    }

    __pipeline_wait_prior(0);
    __syncthreads();

    int r2 = lane >> 1, cB = (lane & 1) * 8;
    float* stw = stP + wrp * 320;
    size_t ob = (size_t)b * 2 * P_;
    for (int i = 0; i < 4; i++) {
        float l0 = 0.f, l1 = 0.f;
        int m = m0 + wm + i * 16 + r2;
        for (int j = 0; j < 2; j++) {
            wmma::store_matrix_sync(stw, acc[i][j], 20, wmma::mem_row_major);
            __syncwarp();
            int n = n0 + wn + j * 16 + cB;
            for (int c = 0; c < 8; c++) {
                float v = fmaxf(stw[r2 * 20 + cB + c] + bias[n + c], 0.f);
                l0 += w2[n + c] * v;
                l1 += w2[256 + n + c] * v;
            }
            __syncwarp();
        }
        atomicAdd(&g_off[ob + m], l0);
        atomicAdd(&g_off[ob + P_ + m], l1);
    }
}

/* ----- bilinear grid-sample (zeros pad), NHWC, bf16-rounded output ------- */
__global__ void sample_kernel() {
    int gid = blockIdx.x * blockDim.x + threadIdx.x;
    int pix = gid >> 5, lane = gid & 31;
    int b = pix >> 12, p = pix & 4095;
    float ox = g_off[b * 2 * P_ + p];
    float oy = g_off[b * 2 * P_ + P_ + p];
    float gx = ox / 63.0f * 2.0f - 1.0f;
    float gy = oy / 63.0f * 2.0f - 1.0f;
    float ix = (gx + 1.0f) * 0.5f * 63.0f;
    float iy = (gy + 1.0f) * 0.5f * 63.0f;
    float x0f = floorf(ix), y0f = floorf(iy);
    float wx1 = ix - x0f, wx0 = 1.0f - wx1;
    float wy1 = iy - y0f, wy0 = 1.0f - wy1;
    int x0 = (int)x0f,          y0 = (int)y0f;
    int x1 = (int)(x0f + 1.0f), y1 = (int)(y0f + 1.0f);
    bool vx0 = (x0 >= 0 && x0 < 64), vx1 = (x1 >= 0 && x1 < 64);
    bool vy0 = (y0 >= 0 && y0 < 64), vy1 = (y1 >= 0 && y1 < 64);
    float e00 = (vy0 && vx0) ? wy0 * wx0 : 0.f;
    float e01 = (vy0 && vx1) ? wy0 * wx1 : 0.f;
    float e10 = (vy1 && vx0) ? wy1 * wx0 : 0.f;
    float e11 = (vy1 && vx1) ? wy1 * wx1 : 0.f;
    int xc0 = min(max(x0, 0), 63), xc1 = min(max(x1, 0), 63);
    int yc0 = min(max(y0, 0), 63), yc1 = min(max(y1, 0), 63);
    const float* base = g_qf + (size_t)b * CP_;
    const float* p00 = base + (size_t)((yc0 << 6) + xc0) * C_;
    const float* p01 = base + (size_t)((yc0 << 6) + xc1) * C_;
    const float* p10 = base + (size_t)((yc1 << 6) + xc0) * C_;
    const float* p11 = base + (size_t)((yc1 << 6) + xc1) * C_;
    size_t o = (size_t)b * CP_ + (size_t)p * C_;
    for (int c = lane; c < C_; c += 32) {
        float v = e00 * p00[c] + e01 * p01[c] + e10 * p10[c] + e11 * p11[c];
        g_sph[o + c] = __float2bfloat16(v);
    }
}

/* ------------------------------ launch ----------------------------------- */
extern "C" void kernel_launch(void* const* d_in, const int* in_sizes, int n_in,
                              void* d_out, int out_size) {
    const float* x_q    = (const float*)d_in[0];
    const float* x_kv   = (const float*)d_in[1];
    const float* n1_w   = (const float*)d_in[2];
    const float* n1_b   = (const float*)d_in[3];
    const float* kv_w   = (const float*)d_in[6];
    const float* kv_b   = (const float*)d_in[7];
    const float* off1_w = (const float*)d_in[8];
    const float* off1_b = (const float*)d_in[9];
    const float* off2_w = (const float*)d_in[10];
    const float* off2_b = (const float*)d_in[11];
    const float* proj_w = (const float*)d_in[12];
    const float* proj_b = (const float*)d_in[13];
    const float* n2_w   = (const float*)d_in[14];
    const float* n2_b   = (const float*)d_in[15];
    const float* fc1_w  = (const float*)d_in[16];
    const float* fc1_b  = (const float*)d_in[17];
    const float* fc2_w  = (const float*)d_in[18];
    const float* fc2_b  = (const float*)d_in[19];

    const int SMEM4  = 4 * 24576;   /* conv: 96KB dynamic */
    const int SMEM4B = 4 * 12288;   /* bf16 gemm: 48KB dynamic */
    static int attr_done = 0;
    if (!attr_done) {
        cudaFuncSetAttribute(conv_wmma, cudaFuncAttributeMaxDynamicSharedMemorySize, SMEM4);
        cudaFuncSetAttribute(gemm_bf16, cudaFuncAttributeMaxDynamicSharedMemorySize, SMEM4B);
        attr_done = 1;
    }

    cudaStream_t s0 = 0;
    static cudaStream_t s1 = 0;
    if (!s1) cudaStreamCreateWithFlags(&s1, cudaStreamNonBlocking);
    static cudaEvent_t evFork = 0, evPrep = 0;
    if (!evFork) {
        cudaEventCreateWithFlags(&evFork, cudaEventDisableTiming);
        cudaEventCreateWithFlags(&evPrep, cudaEventDisableTiming);
    }

    cudaEventRecord(evFork, s0);
    cudaStreamWaitEvent(s1, evFork, 0);
    prep_conv_w<<<(C_ * KC_ + 255) / 256, 256, 0, s1>>>(off1_w);
    prep_split<<<(1024 * C_ + 255) / 256, 256, 0, s1>>>(fc1_w, 1024 * C_, 1);
    prep_split<<<(C_ * 1024 + 255) / 256, 256, 0, s1>>>(fc2_w, C_ * 1024, 2);
    combine_w_t<<<dim3(16, 16), dim3(16, 16), 0, s1>>>(proj_w, kv_w);
    combine_b<<<1, 256, 0, s1>>>(proj_w, proj_b, kv_b);
    init_off<<<(B_ * 2 * P_ + 255) / 256, 256, 0, s1>>>(off2_b);
    cudaEventRecord(evPrep, s1);

    gn_reduce2<<<dim3(64, 8, 2), 256, 0, s0>>>(x_q, x_kv, 0, 0);
    finalize_stats<<<16, 64, 0, s0>>>(0);
    gn_apply_fused<<<dim3(128, 8, 16), dim3(32, 8), 0, s0>>>(x_q, x_kv, n1_w, n1_b);
    cudaStreamWaitEvent(s0, evPrep, 0);
    conv_wmma<<<dim3(32, 2, 8), 256, SMEM4, s0>>>(off1_b, off2_w);
    sample_kernel<<<(B_ * P_ * 32) / 256, 256, 0, s0>>>();
    gemm_bf16<<<dim3(32, 2, 8), 256, SMEM4B, s0>>>(1, (const float*)0, x_q, (float*)0);

    gn_reduce2<<<dim3(64, 8, 1), 256, 0, s0>>>((const float*)0, (const float*)0, 16, 1);
    finalize_stats<<<8, 64, 0, s0>>>(16);
    gn2_apply<<<dim3(512, 8), 256, 0, s0>>>(16, n2_w, n2_b);
    gemm_bf16<<<dim3(32, 8, 8), 256, SMEM4B, s0>>>(2, fc1_b, (const float*)0, (float*)0);
    gemm_bf16<<<dim3(32, 2, 8), 256, SMEM4B, s0>>>(3, fc2_b, (const float*)0, (float*)d_out);
}